// round 1
// baseline (speedup 1.0000x reference)
#include <cuda_runtime.h>
#include <cstdint>

typedef unsigned long long ull;

#define LOCN   40001
#define BATCH  1024
#define TSTEPS 256

// ---------------- device scratch (static globals; no allocations) ----------------
__device__ float g_Gloc[(size_t)LOCN * 600];            // ~96 MB: emb_loc @ [W_ih|W_xt|W_xs] + biases
__device__ float g_Pt[92 * 100];                        // emb_t @ W_tt
__device__ float g_Ps[92 * 100];                        // emb_s @ W_ss
__device__ float g_scr[(size_t)TSTEPS * BATCH * 500];   // ~524 MB: [t][b][ i(100) f g o tsg ]

// ---------------- helpers ----------------
__device__ __forceinline__ float sigf(float x) { return 1.f / (1.f + __expf(-x)); }
// NaN-safe fast tanh: x>>0 -> 1, x<<0 -> -1
__device__ __forceinline__ float tanh_fast(float x) { return 1.f - 2.f / (1.f + __expf(2.f * x)); }

__device__ __forceinline__ ull pack2(float lo, float hi) {
    ull r;
    asm("mov.b64 %0, {%1, %2};" : "=l"(r) : "f"(lo), "f"(hi));
    return r;
}
__device__ __forceinline__ void unpack2(ull v, float& lo, float& hi) {
    asm("mov.b64 {%0, %1}, %2;" : "=f"(lo), "=f"(hi) : "l"(v));
}
// packed fp32x2 FMA (Blackwell): acc.xy += a.xy * b.xy
__device__ __forceinline__ void fma2(ull& acc, ull a, ull b) {
    asm("fma.rn.f32x2 %0, %1, %2, %0;" : "+l"(acc) : "l"(a), "l"(b));
}

// =======================================================================
// Kernel A: Gloc[loc][0:600] = emb_loc[loc][:] @ [W_ih | W_xt | W_xs] + [b | b_t | b_s]
// Tile 64 rows x 64 cols, K=100 split in 2 phases of 50 (smem <= 48KB).
// =======================================================================
__global__ void kernA(const float* __restrict__ emb_loc,
                      const float* __restrict__ W_ih,
                      const float* __restrict__ W_xt,
                      const float* __restrict__ W_xs,
                      const float* __restrict__ b,
                      const float* __restrict__ b_t,
                      const float* __restrict__ b_s)
{
    __shared__ __align__(16) float As[50 * 64];
    __shared__ __align__(16) float Bs[50 * 64];

    const int tid = threadIdx.x;              // 256 threads
    const int m0 = blockIdx.x * 64;
    const int n0 = blockIdx.y * 64;
    const int tx = tid & 15, ty = tid >> 4;
    const int r0 = ty * 4, c0 = tx * 4;

    ull acc[4][2];
#pragma unroll
    for (int i = 0; i < 4; i++) { acc[i][0] = 0ull; acc[i][1] = 0ull; }

    for (int kp = 0; kp < 100; kp += 50) {
        // load A tile: 64 rows x 50 k (coalesced along k)
        for (int i = tid; i < 64 * 50; i += 256) {
            int r = i / 50, k = i % 50;
            int row = m0 + r;
            float v = (row < LOCN) ? emb_loc[(size_t)row * 100 + kp + k] : 0.f;
            As[k * 64 + r] = v;
        }
        // load B tile: 50 k x 64 cols (coalesced along c)
        for (int i = tid; i < 64 * 50; i += 256) {
            int k = i / 64, c = i % 64;
            int col = n0 + c;
            int kk = kp + k;
            float v = 0.f;
            if (col < 400)      v = W_ih[kk * 400 + col];
            else if (col < 500) v = W_xt[kk * 100 + (col - 400)];
            else if (col < 600) v = W_xs[kk * 100 + (col - 500)];
            Bs[k * 64 + c] = v;
        }
        __syncthreads();

#pragma unroll 5
        for (int k = 0; k < 50; k++) {
            float4 a4 = *(const float4*)(As + k * 64 + r0);
            ulonglong2 bv = *(const ulonglong2*)(Bs + k * 64 + c0);
            ull a0 = pack2(a4.x, a4.x);
            ull a1 = pack2(a4.y, a4.y);
            ull a2 = pack2(a4.z, a4.z);
            ull a3 = pack2(a4.w, a4.w);
            fma2(acc[0][0], a0, bv.x); fma2(acc[0][1], a0, bv.y);
            fma2(acc[1][0], a1, bv.x); fma2(acc[1][1], a1, bv.y);
            fma2(acc[2][0], a2, bv.x); fma2(acc[2][1], a2, bv.y);
            fma2(acc[3][0], a3, bv.x); fma2(acc[3][1], a3, bv.y);
        }
        __syncthreads();
    }

    // bias + store
    float bias[4];
#pragma unroll
    for (int p = 0; p < 4; p++) {
        int col = n0 + c0 + p;
        float bv = 0.f;
        if (col < 400)      bv = b[col];
        else if (col < 500) bv = b_t[col - 400];
        else if (col < 600) bv = b_s[col - 500];
        bias[p] = bv;
    }
#pragma unroll
    for (int r = 0; r < 4; r++) {
        int row = m0 + r0 + r;
        if (row >= LOCN) continue;
        float v0, v1, v2, v3;
        unpack2(acc[r][0], v0, v1);
        unpack2(acc[r][1], v2, v3);
        float v[4] = { v0 + bias[0], v1 + bias[1], v2 + bias[2], v3 + bias[3] };
#pragma unroll
        for (int p = 0; p < 4; p++) {
            int col = n0 + c0 + p;
            if (col < 600) g_Gloc[(size_t)row * 600 + col] = v[p];
        }
    }
}

// =======================================================================
// Kernel B: P_t = emb_t @ W_tt ; P_s = emb_s @ W_ss   (92x12 @ 12x100)
// =======================================================================
__global__ void kernB(const float* __restrict__ emb_t, const float* __restrict__ W_tt,
                      const float* __restrict__ emb_s, const float* __restrict__ W_ss)
{
    int i = blockIdx.x * blockDim.x + threadIdx.x;
    if (i >= 92 * 100 * 2) return;
    int which = i / 9200;
    int r = i % 9200;
    int s = r / 100, j = r % 100;
    const float* e = which ? emb_s : emb_t;
    const float* W = which ? W_ss : W_tt;
    float acc = 0.f;
#pragma unroll
    for (int d = 0; d < 12; d++) acc += e[s * 12 + d] * W[d * 100 + j];
    (which ? g_Ps : g_Pt)[s * 100 + j] = acc;
}

// =======================================================================
// Kernel C: per token (b,t): gather Gloc row, compute tsg = sig(pre_t)*sig(pre_s),
// write scratch [t][b][500] = [ gate pre-activations (400) | tsg (100) ].
// One warp per token, 8 tokens per 256-thread block.
// =======================================================================
__global__ void kernC(const int* __restrict__ traj,
                      const int* __restrict__ tu, const int* __restrict__ tl,
                      const int* __restrict__ tu_slot, const int* __restrict__ tl_slot,
                      const int* __restrict__ su, const int* __restrict__ sl,
                      const int* __restrict__ su_slot, const int* __restrict__ sl_slot)
{
    const int w = threadIdx.x >> 5, lane = threadIdx.x & 31;
    const int token = blockIdx.x * 8 + w;               // < 262144 exactly
    const int bb = token >> 8, t = token & 255;         // traj is [B][T] row-major

    const int idx = traj[token];
    const float ut = (float)tu_slot[token], lt = (float)tl_slot[token];
    const float us = (float)su_slot[token], ls = (float)sl_slot[token];
    const float rdt = 1.f / fmaxf(ut + lt, 1.f);
    const float rds = 1.f / fmaxf(us + ls, 1.f);
    const float* Ptl = g_Pt + tl[token] * 100;
    const float* Ptu = g_Pt + tu[token] * 100;
    const float* Psl = g_Ps + sl[token] * 100;
    const float* Psu = g_Ps + su[token] * 100;

    const float* g = g_Gloc + (size_t)idx * 600;
    float* o = g_scr + ((size_t)t * BATCH + bb) * 500;

    // copy 400 gate pre-activations as float4
    const float4* g4 = (const float4*)g;
    float4* o4 = (float4*)o;
    for (int q = lane; q < 100; q += 32) o4[q] = g4[q];

    // tsg
    for (int j = lane; j < 100; j += 32) {
        float pt = g[400 + j] + (ut * Ptl[j] + lt * Ptu[j]) * rdt;
        float ps = g[500 + j] + (us * Psl[j] + ls * Psu[j]) * rds;
        o[400 + j] = sigf(pt) * sigf(ps);
    }
}

// =======================================================================
// Kernel D: persistent recurrence. 147 CTAs x up to 7 batch rows.
// 416 threads: tid = j*4 + kq ; thread holds W_hh[:, {j,100+j,200+j,300+j}] for
// k = kq + 4m (m<25) in registers as f32x2 pairs. h double-buffered in smem as
// duplicated float2. fma.rn.f32x2 for 2x fp32 rate, shfl_xor reduce over kq.
// =======================================================================
__global__ void __launch_bounds__(416, 1)
kernD(const float* __restrict__ W_hh, float* __restrict__ out)
{
    __shared__ __align__(16) float2 hbuf[2][7][100];

    const int tid = threadIdx.x;
    const int j = tid >> 2, kq = tid & 3;
    const bool active = (j < 100);
    const int row0 = blockIdx.x * 7;
    const int R = min(7, BATCH - row0);

    // weights -> registers (one copy of W_hh per SM, spread over threads)
    ull wif[25], wgo[25];
#pragma unroll
    for (int m = 0; m < 25; m++) {
        int k = kq + 4 * m;
        float a = 0.f, bf = 0.f, c = 0.f, d = 0.f;
        if (active) {
            const float* wr = W_hh + k * 400;
            a = wr[j]; bf = wr[100 + j]; c = wr[200 + j]; d = wr[300 + j];
        }
        wif[m] = pack2(a, bf);
        wgo[m] = pack2(c, d);
    }

    // zero h buffer 0
    {
        float2* p = &hbuf[0][0][0];
        for (int i = tid; i < 7 * 100; i += 416) p[i] = make_float2(0.f, 0.f);
    }
    float creg[7];
#pragma unroll
    for (int r = 0; r < 7; r++) creg[r] = 0.f;
    __syncthreads();

    for (int t = 0; t < TSTEPS; t++) {
        const float2(*hc)[100] = hbuf[t & 1];
        float2(*hn)[100] = hbuf[(t + 1) & 1];
        const float* sb = g_scr + ((size_t)t * BATCH + row0) * 500;

#pragma unroll
        for (int r = 0; r < 7; r++) {
            if (r < R) {
                // pre-activations for this (row, j): issued early, consumed after k-loop
                float p0 = 0.f, p1 = 0.f, p2 = 0.f, p3 = 0.f, p4 = 0.f;
                if (active) {
                    const float* pb = sb + r * 500 + j;
                    p0 = __ldg(pb);
                    p1 = __ldg(pb + 100);
                    p2 = __ldg(pb + 200);
                    p3 = __ldg(pb + 300);
                    p4 = __ldg(pb + 400);
                }

                const ull* hrow = (const ull*)(hc[r]);   // duplicated (h,h) pairs
                ull aif = 0ull, ago = 0ull;
#pragma unroll
                for (int m = 0; m < 25; m++) {
                    ull h2 = hrow[kq + 4 * m];
                    fma2(aif, wif[m], h2);
                    fma2(ago, wgo[m], h2);
                }

                float ai, af, ag, ao;
                unpack2(aif, ai, af);
                unpack2(ago, ag, ao);
                // reduce the 4 k-quarters (kq groups are 4 adjacent lanes)
#pragma unroll
                for (int dlt = 1; dlt < 4; dlt <<= 1) {
                    ai += __shfl_xor_sync(0xffffffffu, ai, dlt);
                    af += __shfl_xor_sync(0xffffffffu, af, dlt);
                    ag += __shfl_xor_sync(0xffffffffu, ag, dlt);
                    ao += __shfl_xor_sync(0xffffffffu, ao, dlt);
                }

                if (kq == 0 && active) {
                    float gi = sigf(ai + p0);
                    float gf = sigf(af + p1);
                    float gg = tanh_fast(ag + p2);
                    float go = sigf(ao + p3);
                    float cN = gf * creg[r] + gi * p4 * gg;
                    creg[r] = cN;
                    float h = go * tanh_fast(cN);
                    hn[r][j] = make_float2(h, h);
                    if (t == TSTEPS - 1) out[(row0 + r) * 100 + j] = h;
                }
            }
        }
        __syncthreads();
    }
}

// =======================================================================
// launch
// =======================================================================
extern "C" void kernel_launch(void* const* d_in, const int* in_sizes, int n_in,
                              void* d_out, int out_size)
{
    (void)in_sizes; (void)n_in; (void)out_size;
    const int*   traj    = (const int*)d_in[0];
    // d_in[1] = lennew (unused), d_in[2] = traj_len (fixed 255)
    const int*   tu      = (const int*)d_in[3];
    const int*   tl      = (const int*)d_in[4];
    const int*   tu_s    = (const int*)d_in[5];
    const int*   tl_s    = (const int*)d_in[6];
    const int*   su      = (const int*)d_in[7];
    const int*   sl      = (const int*)d_in[8];
    const int*   su_s    = (const int*)d_in[9];
    const int*   sl_s    = (const int*)d_in[10];
    const float* emb_loc = (const float*)d_in[11];
    const float* emb_t   = (const float*)d_in[12];
    const float* emb_s   = (const float*)d_in[13];
    const float* W_ih    = (const float*)d_in[14];
    const float* W_hh    = (const float*)d_in[15];
    const float* b       = (const float*)d_in[16];
    const float* W_xt    = (const float*)d_in[17];
    const float* W_tt    = (const float*)d_in[18];
    const float* b_t     = (const float*)d_in[19];
    const float* W_xs    = (const float*)d_in[20];
    const float* W_ss    = (const float*)d_in[21];
    const float* b_s     = (const float*)d_in[22];
    float* out = (float*)d_out;

    // A: location-table GEMM (40001 x 600)
    dim3 gA((LOCN + 63) / 64, 10);
    kernA<<<gA, 256>>>(emb_loc, W_ih, W_xt, W_xs, b, b_t, b_s);

    // B: tiny slot-table GEMMs
    kernB<<<(92 * 100 * 2 + 255) / 256, 256>>>(emb_t, W_tt, emb_s, W_ss);

    // C: per-token gather + tsg -> scratch
    kernC<<<(BATCH * TSTEPS) / 8, 256>>>(traj, tu, tl, tu_s, tl_s, su, sl, su_s, sl_s);

    // D: recurrence
    kernD<<<(BATCH + 6) / 7, 416>>>(W_hh, out);
}

// round 2
// speedup vs baseline: 1.2595x; 1.2595x over previous
#include <cuda_runtime.h>
#include <cstdint>

typedef unsigned long long ull;

#define LOCN   40001
#define BATCH  1024
#define TSTEPS 256

#define ROWS_PER_CTA 7
#define NCTA ((BATCH + ROWS_PER_CTA - 1) / ROWS_PER_CTA)   // 147
#define HSTRIDE 104      // padded h row length (floats), 104*4 = 416 B (8B aligned per kq chunk)
#define KPT 26           // k-range per kq thread
#define NPAIR 13         // 26/2 fma2 pairs
#define SCR_BYTES (ROWS_PER_CTA * 500 * 4)   // 14000, multiple of 16

// ---------------- device scratch (static globals; no allocations) ----------------
__device__ float g_Gloc[(size_t)LOCN * 600];            // emb_loc @ [W_ih|W_xt|W_xs] + biases
__device__ float g_Pt[92 * 100];
__device__ float g_Ps[92 * 100];
// pad tail: last CTA's bulk copy overreads (147*7=1029 > 1024 rows)
__device__ float g_scr[(size_t)TSTEPS * BATCH * 500 + 4096];

// ---------------- helpers ----------------
__device__ __forceinline__ float sigf(float x) { return 1.f / (1.f + __expf(-x)); }
__device__ __forceinline__ float tanh_fast(float x) { return 1.f - 2.f / (1.f + __expf(2.f * x)); }

__device__ __forceinline__ ull pack2(float lo, float hi) {
    ull r; asm("mov.b64 %0, {%1, %2};" : "=l"(r) : "f"(lo), "f"(hi)); return r;
}
__device__ __forceinline__ void unpack2(ull v, float& lo, float& hi) {
    asm("mov.b64 {%0, %1}, %2;" : "=f"(lo), "=f"(hi) : "l"(v));
}
__device__ __forceinline__ void fma2(ull& acc, ull a, ull b) {
    asm("fma.rn.f32x2 %0, %1, %2, %0;" : "+l"(acc) : "l"(a), "l"(b));
}
__device__ __forceinline__ uint32_t smem_u32(const void* p) {
    uint32_t a;
    asm("{ .reg .u64 t; cvta.to.shared.u64 t, %1; cvt.u32.u64 %0, t; }" : "=r"(a) : "l"(p));
    return a;
}
__device__ __forceinline__ void mbar_init(uint32_t mbar, uint32_t cnt) {
    asm volatile("mbarrier.init.shared.b64 [%0], %1;" :: "r"(mbar), "r"(cnt) : "memory");
}
__device__ __forceinline__ void mbar_expect_tx(uint32_t mbar, uint32_t bytes) {
    asm volatile("mbarrier.arrive.expect_tx.shared.b64 _, [%0], %1;" :: "r"(mbar), "r"(bytes) : "memory");
}
__device__ __forceinline__ void bulk_g2s(uint32_t dst, const void* src, uint32_t bytes, uint32_t mbar) {
    asm volatile("cp.async.bulk.shared::cta.global.mbarrier::complete_tx::bytes [%0], [%1], %2, [%3];"
                 :: "r"(dst), "l"(src), "r"(bytes), "r"(mbar) : "memory");
}
__device__ __forceinline__ void mbar_wait(uint32_t mbar, uint32_t parity) {
    uint32_t done;
    asm volatile("{\n\t.reg .pred p;\n\t"
                 "mbarrier.try_wait.parity.acquire.cta.shared::cta.b64 p, [%1], %2;\n\t"
                 "selp.b32 %0, 1, 0, p;\n\t}"
                 : "=r"(done) : "r"(mbar), "r"(parity) : "memory");
    if (!done) {
        asm volatile("{\n\t.reg .pred P1;\n\t"
                     "WL_%=:\n\t"
                     "mbarrier.try_wait.parity.acquire.cta.shared::cta.b64 P1, [%0], %1, 0x989680;\n\t"
                     "@P1 bra.uni WD_%=;\n\t"
                     "bra.uni WL_%=;\n\t"
                     "WD_%=:\n\t}"
                     :: "r"(mbar), "r"(parity) : "memory");
    }
}

// =======================================================================
// Kernel A: Gloc[loc][0:600] = emb_loc @ [W_ih|W_xt|W_xs] + biases
// =======================================================================
__global__ void kernA(const float* __restrict__ emb_loc,
                      const float* __restrict__ W_ih,
                      const float* __restrict__ W_xt,
                      const float* __restrict__ W_xs,
                      const float* __restrict__ b,
                      const float* __restrict__ b_t,
                      const float* __restrict__ b_s)
{
    __shared__ __align__(16) float As[50 * 64];
    __shared__ __align__(16) float Bs[50 * 64];

    const int tid = threadIdx.x;
    const int m0 = blockIdx.x * 64;
    const int n0 = blockIdx.y * 64;
    const int tx = tid & 15, ty = tid >> 4;
    const int r0 = ty * 4, c0 = tx * 4;

    ull acc[4][2];
#pragma unroll
    for (int i = 0; i < 4; i++) { acc[i][0] = 0ull; acc[i][1] = 0ull; }

    for (int kp = 0; kp < 100; kp += 50) {
        for (int i = tid; i < 64 * 50; i += 256) {
            int r = i / 50, k = i % 50;
            int row = m0 + r;
            As[k * 64 + r] = (row < LOCN) ? emb_loc[(size_t)row * 100 + kp + k] : 0.f;
        }
        for (int i = tid; i < 64 * 50; i += 256) {
            int k = i / 64, c = i % 64;
            int col = n0 + c, kk = kp + k;
            float v = 0.f;
            if (col < 400)      v = W_ih[kk * 400 + col];
            else if (col < 500) v = W_xt[kk * 100 + (col - 400)];
            else if (col < 600) v = W_xs[kk * 100 + (col - 500)];
            Bs[k * 64 + c] = v;
        }
        __syncthreads();

#pragma unroll 5
        for (int k = 0; k < 50; k++) {
            float4 a4 = *(const float4*)(As + k * 64 + r0);
            ulonglong2 bv = *(const ulonglong2*)(Bs + k * 64 + c0);
            ull a0 = pack2(a4.x, a4.x);
            ull a1 = pack2(a4.y, a4.y);
            ull a2 = pack2(a4.z, a4.z);
            ull a3 = pack2(a4.w, a4.w);
            fma2(acc[0][0], a0, bv.x); fma2(acc[0][1], a0, bv.y);
            fma2(acc[1][0], a1, bv.x); fma2(acc[1][1], a1, bv.y);
            fma2(acc[2][0], a2, bv.x); fma2(acc[2][1], a2, bv.y);
            fma2(acc[3][0], a3, bv.x); fma2(acc[3][1], a3, bv.y);
        }
        __syncthreads();
    }

    float bias[4];
#pragma unroll
    for (int p = 0; p < 4; p++) {
        int col = n0 + c0 + p;
        float bv = 0.f;
        if (col < 400)      bv = b[col];
        else if (col < 500) bv = b_t[col - 400];
        else if (col < 600) bv = b_s[col - 500];
        bias[p] = bv;
    }
#pragma unroll
    for (int r = 0; r < 4; r++) {
        int row = m0 + r0 + r;
        if (row >= LOCN) continue;
        float v0, v1, v2, v3;
        unpack2(acc[r][0], v0, v1);
        unpack2(acc[r][1], v2, v3);
        float v[4] = { v0 + bias[0], v1 + bias[1], v2 + bias[2], v3 + bias[3] };
#pragma unroll
        for (int p = 0; p < 4; p++) {
            int col = n0 + c0 + p;
            if (col < 600) g_Gloc[(size_t)row * 600 + col] = v[p];
        }
    }
}

// =======================================================================
// Kernel B: P_t = emb_t @ W_tt ; P_s = emb_s @ W_ss
// =======================================================================
__global__ void kernB(const float* __restrict__ emb_t, const float* __restrict__ W_tt,
                      const float* __restrict__ emb_s, const float* __restrict__ W_ss)
{
    int i = blockIdx.x * blockDim.x + threadIdx.x;
    if (i >= 92 * 100 * 2) return;
    int which = i / 9200;
    int r = i % 9200;
    int s = r / 100, j = r % 100;
    const float* e = which ? emb_s : emb_t;
    const float* W = which ? W_ss : W_tt;
    float acc = 0.f;
#pragma unroll
    for (int d = 0; d < 12; d++) acc += e[s * 12 + d] * W[d * 100 + j];
    (which ? g_Ps : g_Pt)[s * 100 + j] = acc;
}

// =======================================================================
// Kernel C: gather Gloc row + tsg -> scratch [t][b][ pre(400) | tsg(100) ]
// =======================================================================
__global__ void kernC(const int* __restrict__ traj,
                      const int* __restrict__ tu, const int* __restrict__ tl,
                      const int* __restrict__ tu_slot, const int* __restrict__ tl_slot,
                      const int* __restrict__ su, const int* __restrict__ sl,
                      const int* __restrict__ su_slot, const int* __restrict__ sl_slot)
{
    const int w = threadIdx.x >> 5, lane = threadIdx.x & 31;
    const int token = blockIdx.x * 8 + w;
    const int bb = token >> 8, t = token & 255;

    const int idx = traj[token];
    const float ut = (float)tu_slot[token], lt = (float)tl_slot[token];
    const float us = (float)su_slot[token], ls = (float)sl_slot[token];
    const float rdt = 1.f / fmaxf(ut + lt, 1.f);
    const float rds = 1.f / fmaxf(us + ls, 1.f);
    const float* Ptl = g_Pt + tl[token] * 100;
    const float* Ptu = g_Pt + tu[token] * 100;
    const float* Psl = g_Ps + sl[token] * 100;
    const float* Psu = g_Ps + su[token] * 100;

    const float* g = g_Gloc + (size_t)idx * 600;
    float* o = g_scr + ((size_t)t * BATCH + bb) * 500;

    const float4* g4 = (const float4*)g;
    float4* o4 = (float4*)o;
    for (int q = lane; q < 100; q += 32) o4[q] = g4[q];

    for (int j = lane; j < 100; j += 32) {
        float pt = g[400 + j] + (ut * Ptl[j] + lt * Ptu[j]) * rdt;
        float ps = g[500 + j] + (us * Psl[j] + ls * Psu[j]) * rds;
        o[400 + j] = sigf(pt) * sigf(ps);
    }
}

// =======================================================================
// Kernel D v2: persistent recurrence, 147 CTAs x 7 rows, 416 threads.
//  - scratch staged 2 steps ahead via cp.async.bulk (14 KB/step) -> zero LDG in loop
//  - h rows padded to 104 floats; thread kq covers k in [26kq, 26kq+26)
//  - k-pair packed fma.rn.f32x2, weights as (k,k+1) pairs per gate in regs
//  - shfl_xor reduce over 4 kq lanes; kq==0 does activations + h write
// =======================================================================
__global__ void __launch_bounds__(416, 1)
kernD(const float* __restrict__ W_hh, float* __restrict__ out)
{
    __shared__ __align__(16) float hbuf[2][ROWS_PER_CTA][HSTRIDE];
    __shared__ __align__(16) float sscr[2][ROWS_PER_CTA * 500];
    __shared__ __align__(8)  ull  smbar[2];

    const int tid = threadIdx.x;
    const int j = tid >> 2, kq = tid & 3;
    const bool active = (j < 100);
    const int row0 = blockIdx.x * ROWS_PER_CTA;

    // ---- weights into registers as (k,k+1) pairs per gate ----
    ull wi[NPAIR], wf[NPAIR], wg[NPAIR], wo[NPAIR];
#pragma unroll
    for (int m = 0; m < NPAIR; m++) {
        int k0 = kq * KPT + 2 * m, k1 = k0 + 1;
        float i0 = 0.f, i1 = 0.f, f0 = 0.f, f1 = 0.f;
        float g0 = 0.f, g1 = 0.f, o0 = 0.f, o1 = 0.f;
        if (active) {
            if (k0 < 100) {
                const float* wr = W_hh + k0 * 400;
                i0 = wr[j]; f0 = wr[100 + j]; g0 = wr[200 + j]; o0 = wr[300 + j];
            }
            if (k1 < 100) {
                const float* wr = W_hh + k1 * 400;
                i1 = wr[j]; f1 = wr[100 + j]; g1 = wr[200 + j]; o1 = wr[300 + j];
            }
        }
        wi[m] = pack2(i0, i1);
        wf[m] = pack2(f0, f1);
        wg[m] = pack2(g0, g1);
        wo[m] = pack2(o0, o1);
    }

    // ---- init: zero both h buffers (incl. padding), init mbarriers ----
    {
        float* p = &hbuf[0][0][0];
        for (int i = tid; i < 2 * ROWS_PER_CTA * HSTRIDE; i += 416) p[i] = 0.f;
    }
    uint32_t mb0 = smem_u32(&smbar[0]);
    uint32_t mb1 = smem_u32(&smbar[1]);
    uint32_t sc0 = smem_u32(&sscr[0][0]);
    uint32_t sc1 = smem_u32(&sscr[1][0]);
    if (tid == 0) { mbar_init(mb0, 1); mbar_init(mb1, 1); }
    __syncthreads();

    const float* scr_base = g_scr + (size_t)row0 * 500;
    if (tid == 0) {
        mbar_expect_tx(mb0, SCR_BYTES);
        bulk_g2s(sc0, scr_base, SCR_BYTES, mb0);
        mbar_expect_tx(mb1, SCR_BYTES);
        bulk_g2s(sc1, scr_base + (size_t)BATCH * 500, SCR_BYTES, mb1);
    }

    float creg[ROWS_PER_CTA];
#pragma unroll
    for (int r = 0; r < ROWS_PER_CTA; r++) creg[r] = 0.f;

#pragma unroll 1
    for (int t = 0; t < TSTEPS; t++) {
        const int buf = t & 1;
        mbar_wait(buf ? mb1 : mb0, (t >> 1) & 1);

        const float* sb = sscr[buf];
        const float* hc = &hbuf[buf][0][0];
        float* hn = &hbuf[buf ^ 1][0][0];

#pragma unroll
        for (int r = 0; r < ROWS_PER_CTA; r++) {
            // pre-activations + tsg (broadcast across kq lanes)
            float p0 = 0.f, p1 = 0.f, p2 = 0.f, p3 = 0.f, p4 = 0.f;
            if (active) {
                const float* pb = sb + r * 500 + j;
                p0 = pb[0]; p1 = pb[100]; p2 = pb[200]; p3 = pb[300]; p4 = pb[400];
            }

            const ull* h2 = (const ull*)(hc + r * HSTRIDE + kq * KPT);
            ull ai2 = 0ull, af2 = 0ull, ag2 = 0ull, ao2 = 0ull;
#pragma unroll
            for (int m = 0; m < NPAIR; m++) {
                ull h = h2[m];
                fma2(ai2, h, wi[m]);
                fma2(af2, h, wf[m]);
                fma2(ag2, h, wg[m]);
                fma2(ao2, h, wo[m]);
            }
            float ai, af, ag, ao, xl, xh;
            unpack2(ai2, xl, xh); ai = xl + xh;
            unpack2(af2, xl, xh); af = xl + xh;
            unpack2(ag2, xl, xh); ag = xl + xh;
            unpack2(ao2, xl, xh); ao = xl + xh;
#pragma unroll
            for (int d = 1; d < 4; d <<= 1) {
                ai += __shfl_xor_sync(0xffffffffu, ai, d);
                af += __shfl_xor_sync(0xffffffffu, af, d);
                ag += __shfl_xor_sync(0xffffffffu, ag, d);
                ao += __shfl_xor_sync(0xffffffffu, ao, d);
            }

            if (kq == 0 && active) {
                float gi = sigf(ai + p0);
                float gf = sigf(af + p1);
                float gg = tanh_fast(ag + p2);
                float go = sigf(ao + p3);
                float cN = gf * creg[r] + gi * p4 * gg;
                creg[r] = cN;
                float h = go * tanh_fast(cN);
                hn[r * HSTRIDE + j] = h;
                if (t == TSTEPS - 1 && row0 + r < BATCH) out[(row0 + r) * 100 + j] = h;
            }
        }
        __syncthreads();

        if (t + 2 < TSTEPS && tid == 0) {
            uint32_t mb = buf ? mb1 : mb0;
            mbar_expect_tx(mb, SCR_BYTES);
            bulk_g2s(buf ? sc1 : sc0, scr_base + (size_t)(t + 2) * BATCH * 500, SCR_BYTES, mb);
        }
    }
}

// =======================================================================
// launch
// =======================================================================
extern "C" void kernel_launch(void* const* d_in, const int* in_sizes, int n_in,
                              void* d_out, int out_size)
{
    (void)in_sizes; (void)n_in; (void)out_size;
    const int*   traj    = (const int*)d_in[0];
    const int*   tu      = (const int*)d_in[3];
    const int*   tl      = (const int*)d_in[4];
    const int*   tu_s    = (const int*)d_in[5];
    const int*   tl_s    = (const int*)d_in[6];
    const int*   su      = (const int*)d_in[7];
    const int*   sl      = (const int*)d_in[8];
    const int*   su_s    = (const int*)d_in[9];
    const int*   sl_s    = (const int*)d_in[10];
    const float* emb_loc = (const float*)d_in[11];
    const float* emb_t   = (const float*)d_in[12];
    const float* emb_s   = (const float*)d_in[13];
    const float* W_ih    = (const float*)d_in[14];
    const float* W_hh    = (const float*)d_in[15];
    const float* b       = (const float*)d_in[16];
    const float* W_xt    = (const float*)d_in[17];
    const float* W_tt    = (const float*)d_in[18];
    const float* b_t     = (const float*)d_in[19];
    const float* W_xs    = (const float*)d_in[20];
    const float* W_ss    = (const float*)d_in[21];
    const float* b_s     = (const float*)d_in[22];
    float* out = (float*)d_out;

    dim3 gA((LOCN + 63) / 64, 10);
    kernA<<<gA, 256>>>(emb_loc, W_ih, W_xt, W_xs, b, b_t, b_s);

    kernB<<<(92 * 100 * 2 + 255) / 256, 256>>>(emb_t, W_tt, emb_s, W_ss);

    kernC<<<(BATCH * TSTEPS) / 8, 256>>>(traj, tu, tl, tu_s, tl_s, su, sl, su_s, sl_s);

    kernD<<<NCTA, 416>>>(W_hh, out);
}